// round 6
// baseline (speedup 1.0000x reference)
#include <cuda_runtime.h>
#include <cstdint>

// Problem dims
#define BB 32
#define SS 64
#define TT 48
#define TM 47      // T-1 decoder steps
#define VV 32000
#define EE 512
#define HH 1024
#define H3 3072
#define H2 2048

#define KC 128          // k-chunk per partial block
#define NSPLIT 8        // k-splits (HH / KC)
#define PARTSZ ((size_t)BB * H3)

// ---------------- scratch (device global, no allocs) ----------------
#define OFF_EMBS   0ull                                   // B*S*E
#define OFF_GI0    (OFF_EMBS   + (size_t)BB*SS*EE)        // [t][b][n] slabs
#define OFF_H0SEQ  (OFF_GI0    + (size_t)BB*SS*H3)        // [b][t][h]
#define OFF_GI1    (OFF_H0SEQ  + (size_t)BB*SS*HH)        // [t][b][n]
#define OFF_ENCOUT (OFF_GI1    + (size_t)BB*SS*H3)        // [b][t][h]
#define OFF_PROJ   (OFF_ENCOUT + (size_t)BB*SS*HH)        // [b][s][h]
#define OFF_EMBT   (OFF_PROJ   + (size_t)BB*SS*HH)        // rows m=t*B+b
#define OFF_EPRE   (OFF_EMBT   + (size_t)TM*BB*EE)        // [t][b][n] slabs
#define OFF_CAT    (OFF_EPRE   + (size_t)TM*BB*H3)        // rows m=t*B+b, [d1|ctx]
#define OFF_H0A    (OFF_CAT    + (size_t)TM*BB*H2)        // state [k][b]
#define OFF_H0B    (OFF_H0A    + (size_t)BB*HH)
#define OFF_H1A    (OFF_H0B    + (size_t)BB*HH)
#define OFF_H1B    (OFF_H1A    + (size_t)BB*HH)
#define OFF_CTXT   (OFF_H1B    + (size_t)BB*HH)           // ctx [k][b]
#define OFF_D1ROW  (OFF_CTXT   + (size_t)BB*HH)           // d1 [b][h]
#define OFF_PART   (OFF_D1ROW  + (size_t)BB*HH)           // 32 partial slabs [b][n]
#define OFF_CNT    (OFF_PART   + 32*PARTSZ)               // 128 ints
#define OFF_WT     (OFF_CNT    + 128)                     // 6 transposed weights [k][n]
#define WT_SZ      ((size_t)HH * H3)
#define SCRATCH_TOTAL (OFF_WT + 6*WT_SZ)

__device__ float g_scratch[SCRATCH_TOTAL];

// ---------------- small helpers ----------------
__device__ __forceinline__ float4 ld4(const float* p) {
    return *reinterpret_cast<const float4*>(p);
}
__device__ __forceinline__ void st4(float* p, float4 v) {
    *reinterpret_cast<float4*>(p) = v;
}
__device__ __forceinline__ float4 add4(float4 a, float4 b) {
    return make_float4(a.x + b.x, a.y + b.y, a.z + b.z, a.w + b.w);
}

__global__ void zero_kernel(float* p, int n) {
    int i = blockIdx.x * blockDim.x + threadIdx.x;
    if (i < n) p[i] = 0.f;
}

__global__ void embed_enc_kernel(const int* __restrict__ ids,
                                 const float* __restrict__ table,
                                 float* __restrict__ out) {
    int i = blockIdx.x * blockDim.x + threadIdx.x;
    if (i >= BB * SS * EE) return;
    int tok = i / EE;
    int e = i % EE;
    out[i] = table[(size_t)ids[tok] * EE + e];
}

__global__ void embed_dec_kernel(const int* __restrict__ tgt,
                                 const float* __restrict__ table,
                                 float* __restrict__ out) {
    int i = blockIdx.x * blockDim.x + threadIdx.x;
    if (i >= TM * BB * EE) return;
    int m = i / EE;
    int e = i % EE;
    int t = m / BB;
    int b = m % BB;
    out[i] = table[(size_t)tgt[b * TT + t] * EE + e];
}

// weight transpose: Wt[k][n] = W[n][koff + k]
__global__ void transpose_w(const float* __restrict__ W, int ldw, int koff,
                            float* __restrict__ Wt) {
    __shared__ float s[32][33];
    int n0 = blockIdx.x * 32, k0 = blockIdx.y * 32;
    int tx = threadIdx.x & 31, ty = threadIdx.x >> 5;
#pragma unroll
    for (int i = 0; i < 4; i++)
        s[ty + i * 8][tx] = W[(size_t)(n0 + ty + i * 8) * ldw + koff + k0 + tx];
    __syncthreads();
#pragma unroll
    for (int i = 0; i < 4; i++)
        Wt[(size_t)(k0 + ty + i * 8) * H3 + n0 + tx] = s[tx][ty + i * 8];
}

// ---------------- tf32 helpers ----------------
__device__ __forceinline__ uint32_t f2tf(float f) {
    uint32_t u;
    asm("cvt.rna.tf32.f32 %0, %1;" : "=r"(u) : "f"(f));
    return u;
}

// ---------------- tf32 GEMM (batched projections; 128x128, 4 warps) ----------------
#define MODE_NORM 0
#define MODE_TENC 2   // m = b*64+t -> [t][b][n] slabs
#define MODE_TDEC 3   // m = t*32+b -> [t][b][n] slabs

template <int MODE>
__global__ void __launch_bounds__(256)
gemm_tf32(const float* __restrict__ A, int lda,
          const float* __restrict__ W, int ldw,
          const float* __restrict__ bias,
          float* __restrict__ C, int M, int N, int K) {
    __shared__ uint32_t As[32][132];   // [k][m]
    __shared__ uint32_t Ws[32][132];   // [k][n]
    const int bm = blockIdx.y * 128, bn = blockIdx.x * 128;
    const int tid = threadIdx.x;
    const int warp = tid >> 5, lane = tid & 31;
    const int wm = (warp & 1) * 64, wn = (warp >> 1) * 32;
    const int g = lane >> 2, tig = lane & 3;

    float acc[4][4][4];
#pragma unroll
    for (int a = 0; a < 4; a++)
#pragma unroll
        for (int b = 0; b < 4; b++)
#pragma unroll
            for (int c = 0; c < 4; c++) acc[a][b][c] = 0.f;

    float4 pa[4], pw[4];
#pragma unroll
    for (int i = 0; i < 4; i++) {
        int e = tid + i * 256;
        int m = e >> 3, kq = (e & 7) * 4;
        float4 v = make_float4(0.f, 0.f, 0.f, 0.f);
        if (bm + m < M) v = ld4(A + (size_t)(bm + m) * lda + kq);
        pa[i] = v;
        pw[i] = ld4(W + (size_t)(bn + m) * ldw + kq);
    }
#pragma unroll
    for (int i = 0; i < 4; i++) {
        int e = tid + i * 256;
        int m = e >> 3, kq = (e & 7) * 4;
        As[kq + 0][m] = f2tf(pa[i].x); As[kq + 1][m] = f2tf(pa[i].y);
        As[kq + 2][m] = f2tf(pa[i].z); As[kq + 3][m] = f2tf(pa[i].w);
        Ws[kq + 0][m] = f2tf(pw[i].x); Ws[kq + 1][m] = f2tf(pw[i].y);
        Ws[kq + 2][m] = f2tf(pw[i].z); Ws[kq + 3][m] = f2tf(pw[i].w);
    }
    __syncthreads();

    for (int k0 = 0; k0 < K; k0 += 32) {
        bool has_next = (k0 + 32) < K;
        if (has_next) {
#pragma unroll
            for (int i = 0; i < 4; i++) {
                int e = tid + i * 256;
                int m = e >> 3, kq = (e & 7) * 4;
                float4 v = make_float4(0.f, 0.f, 0.f, 0.f);
                if (bm + m < M) v = ld4(A + (size_t)(bm + m) * lda + k0 + 32 + kq);
                pa[i] = v;
                pw[i] = ld4(W + (size_t)(bn + m) * ldw + k0 + 32 + kq);
            }
        }
#pragma unroll
        for (int kk = 0; kk < 32; kk += 8) {
            uint32_t af[4][4];
#pragma unroll
            for (int mt = 0; mt < 4; mt++) {
                int ml = wm + mt * 16 + g;
                af[mt][0] = As[kk + tig][ml];
                af[mt][1] = As[kk + tig][ml + 8];
                af[mt][2] = As[kk + tig + 4][ml];
                af[mt][3] = As[kk + tig + 4][ml + 8];
            }
            uint32_t bf[4][2];
#pragma unroll
            for (int nt = 0; nt < 4; nt++) {
                int nl = wn + nt * 8 + g;
                bf[nt][0] = Ws[kk + tig][nl];
                bf[nt][1] = Ws[kk + tig + 4][nl];
            }
#pragma unroll
            for (int mt = 0; mt < 4; mt++)
#pragma unroll
                for (int nt = 0; nt < 4; nt++) {
                    asm volatile(
                        "mma.sync.aligned.m16n8k8.row.col.f32.tf32.tf32.f32 "
                        "{%0,%1,%2,%3}, {%4,%5,%6,%7}, {%8,%9}, {%0,%1,%2,%3};\n"
                        : "+f"(acc[mt][nt][0]), "+f"(acc[mt][nt][1]),
                          "+f"(acc[mt][nt][2]), "+f"(acc[mt][nt][3])
                        : "r"(af[mt][0]), "r"(af[mt][1]), "r"(af[mt][2]), "r"(af[mt][3]),
                          "r"(bf[nt][0]), "r"(bf[nt][1]));
                }
        }
        __syncthreads();
        if (has_next) {
#pragma unroll
            for (int i = 0; i < 4; i++) {
                int e = tid + i * 256;
                int m = e >> 3, kq = (e & 7) * 4;
                As[kq + 0][m] = f2tf(pa[i].x); As[kq + 1][m] = f2tf(pa[i].y);
                As[kq + 2][m] = f2tf(pa[i].z); As[kq + 3][m] = f2tf(pa[i].w);
                Ws[kq + 0][m] = f2tf(pw[i].x); Ws[kq + 1][m] = f2tf(pw[i].y);
                Ws[kq + 2][m] = f2tf(pw[i].z); Ws[kq + 3][m] = f2tf(pw[i].w);
            }
            __syncthreads();
        }
    }

#pragma unroll
    for (int mt = 0; mt < 4; mt++) {
#pragma unroll
        for (int i2 = 0; i2 < 2; i2++) {
            int m = bm + wm + mt * 16 + g + i2 * 8;
            if (m >= M) continue;
#pragma unroll
            for (int nt = 0; nt < 4; nt++) {
#pragma unroll
                for (int j = 0; j < 2; j++) {
                    int n = bn + wn + nt * 8 + tig * 2 + j;
                    float v = acc[mt][nt][i2 * 2 + j];
                    if (bias) v += bias[n];
                    if (MODE == MODE_NORM) {
                        C[(size_t)m * N + n] = v;
                    } else if (MODE == MODE_TENC) {
                        int t = m & 63, b = m >> 6;
                        C[((size_t)t * 32 + b) * N + n] = v;
                    } else {  // MODE_TDEC
                        int t = m >> 5, b = m & 31;
                        C[((size_t)t * 32 + b) * N + n] = v;
                    }
                }
            }
        }
    }
}

// ---------------- final projection: 128x256 tile, 8 warps, m-major grid ----------------
// smem layout [m][k] stride 36 words: conflict-free STS.128 and frag LDS.
#define FSM_WORDS (128 * 36 + 256 * 36)
#define FSM_BYTES (FSM_WORDS * 4)

__global__ void __launch_bounds__(256)
gemm_final(const float* __restrict__ A, int lda,
           const float* __restrict__ W, int ldw,
           const float* __restrict__ bias,
           float* __restrict__ C, int M, int N, int K) {
    extern __shared__ uint32_t sm[];
    uint32_t* As = sm;               // [128][36]
    uint32_t* Ws = sm + 128 * 36;    // [256][36]
    const int bm = blockIdx.x * 128;   // m-major: W streams from DRAM once
    const int bn = blockIdx.y * 256;
    const int tid = threadIdx.x;
    const int warp = tid >> 5, lane = tid & 31;
    const int wm = (warp & 1) * 64, wn = (warp >> 1) * 64;
    const int g = lane >> 2, tig = lane & 3;

    float acc[4][8][4];
#pragma unroll
    for (int a = 0; a < 4; a++)
#pragma unroll
        for (int b = 0; b < 8; b++)
#pragma unroll
            for (int c = 0; c < 4; c++) acc[a][b][c] = 0.f;

    const int lm = tid >> 3;            // 0..31 base row for A loads (m = lm + i*32? no)
    const int kq = (tid & 7) * 4;
    (void)lm;

    float4 pa[4], pw[8];

#define LDA_CHUNK(K0)                                                        \
    _Pragma("unroll") for (int i = 0; i < 4; i++) {                          \
        int e = tid + i * 256;                                               \
        int m = e >> 3;                                                      \
        float4 v = make_float4(0.f, 0.f, 0.f, 0.f);                          \
        if (bm + m < M) v = ld4(A + (size_t)(bm + m) * lda + (K0) + kq);     \
        pa[i] = v;                                                           \
    }
#define LDW_CHUNK(K0)                                                        \
    _Pragma("unroll") for (int i = 0; i < 8; i++) {                          \
        int e = tid + i * 256;                                               \
        int n = e >> 3;                                                      \
        pw[i] = ld4(W + (size_t)(bn + n) * ldw + (K0) + kq);                 \
    }
#define ST_CHUNK()                                                           \
    _Pragma("unroll") for (int i = 0; i < 4; i++) {                          \
        int e = tid + i * 256;                                               \
        int m = e >> 3;                                                      \
        uint4 u = make_uint4(f2tf(pa[i].x), f2tf(pa[i].y),                   \
                             f2tf(pa[i].z), f2tf(pa[i].w));                  \
        *reinterpret_cast<uint4*>(&As[m * 36 + kq]) = u;                     \
    }                                                                        \
    _Pragma("unroll") for (int i = 0; i < 8; i++) {                          \
        int e = tid + i * 256;                                               \
        int n = e >> 3;                                                      \
        uint4 u = make_uint4(f2tf(pw[i].x), f2tf(pw[i].y),                   \
                             f2tf(pw[i].z), f2tf(pw[i].w));                  \
        *reinterpret_cast<uint4*>(&Ws[n * 36 + kq]) = u;                     \
    }

    LDA_CHUNK(0)
    LDW_CHUNK(0)
    ST_CHUNK()
    __syncthreads();

    for (int k0 = 0; k0 < K; k0 += 32) {
        bool has_next = (k0 + 32) < K;
        if (has_next) {
            LDA_CHUNK(k0 + 32)
            LDW_CHUNK(k0 + 32)
        }
#pragma unroll
        for (int kk = 0; kk < 32; kk += 8) {
            uint32_t af[4][4];
#pragma unroll
            for (int mt = 0; mt < 4; mt++) {
                int ml = wm + mt * 16 + g;
                af[mt][0] = As[ml * 36 + kk + tig];
                af[mt][1] = As[(ml + 8) * 36 + kk + tig];
                af[mt][2] = As[ml * 36 + kk + tig + 4];
                af[mt][3] = As[(ml + 8) * 36 + kk + tig + 4];
            }
            uint32_t bf[8][2];
#pragma unroll
            for (int nt = 0; nt < 8; nt++) {
                int nl = wn + nt * 8 + g;
                bf[nt][0] = Ws[nl * 36 + kk + tig];
                bf[nt][1] = Ws[nl * 36 + kk + tig + 4];
            }
#pragma unroll
            for (int mt = 0; mt < 4; mt++)
#pragma unroll
                for (int nt = 0; nt < 8; nt++) {
                    asm volatile(
                        "mma.sync.aligned.m16n8k8.row.col.f32.tf32.tf32.f32 "
                        "{%0,%1,%2,%3}, {%4,%5,%6,%7}, {%8,%9}, {%0,%1,%2,%3};\n"
                        : "+f"(acc[mt][nt][0]), "+f"(acc[mt][nt][1]),
                          "+f"(acc[mt][nt][2]), "+f"(acc[mt][nt][3])
                        : "r"(af[mt][0]), "r"(af[mt][1]), "r"(af[mt][2]), "r"(af[mt][3]),
                          "r"(bf[nt][0]), "r"(bf[nt][1]));
                }
        }
        __syncthreads();
        if (has_next) {
            ST_CHUNK()
            __syncthreads();
        }
    }

    // epilogue: rows m = t*32+b -> out row b*TM + t
#pragma unroll
    for (int mt = 0; mt < 4; mt++) {
#pragma unroll
        for (int i2 = 0; i2 < 2; i2++) {
            int m = bm + wm + mt * 16 + g + i2 * 8;
            if (m >= M) continue;
            int b = m & 31, t = m >> 5;
            float* cr = C + (size_t)(b * TM + t) * N;
#pragma unroll
            for (int nt = 0; nt < 8; nt++) {
#pragma unroll
                for (int j = 0; j < 2; j++) {
                    int n = bn + wn + nt * 8 + tig * 2 + j;
                    cr[n] = acc[mt][nt][i2 * 2 + j] + bias[n];
                }
            }
        }
    }
#undef LDA_CHUNK
#undef LDW_CHUNK
#undef ST_CHUNK
}

// ---------------- recurrent partial: 32 cols x 3 gates over a KC k-chunk ----------------
// A [k][b] (stride 32), Wt [k][n] (stride H3). Writes slab [b][n].
__device__ __forceinline__ void rec_partial(
    const float* __restrict__ A, const float* __restrict__ Wt,
    float* __restrict__ slab, float* sA, int tid, int c0, int k0) {
    const float4* src = reinterpret_cast<const float4*>(A + (size_t)k0 * 32);
#pragma unroll
    for (int i = 0; i < 4; i++)
        reinterpret_cast<float4*>(sA)[tid + i * 256] = src[tid + i * 256];
    __syncthreads();
    const int cc = c0 + (tid & 7) * 4;
    const int b = tid >> 3;
    float4 a0 = make_float4(0.f, 0.f, 0.f, 0.f);
    float4 a1 = a0, a2 = a0;
    const float* wp = Wt + (size_t)k0 * H3 + cc;
#pragma unroll 4
    for (int k = 0; k < KC; k++) {
        float a = sA[k * 32 + b];
        float4 w0 = ld4(wp + (size_t)k * H3);
        float4 w1 = ld4(wp + (size_t)k * H3 + HH);
        float4 w2 = ld4(wp + (size_t)k * H3 + 2 * HH);
        a0.x += a * w0.x; a0.y += a * w0.y; a0.z += a * w0.z; a0.w += a * w0.w;
        a1.x += a * w1.x; a1.y += a * w1.y; a1.z += a * w1.z; a1.w += a * w1.w;
        a2.x += a * w2.x; a2.y += a * w2.y; a2.z += a * w2.z; a2.w += a * w2.w;
    }
    float* P = slab + (size_t)b * H3 + cc;
    st4(P, a0);
    st4(P + HH, a1);
    st4(P + 2 * HH, a2);
}

// ---------------- fused gate for a 32-col bundle (winner block) ----------------
__device__ __forceinline__ void gate_bundle(
    int tid, int c0,
    const float* __restrict__ partH,     // NSPLIT slabs
    const float* __restrict__ partX,     // NSPLIT slabs or null
    const float* __restrict__ gi_slab,   // [b][n] or null
    const float* __restrict__ gi_vec,    // or null
    const float* __restrict__ bhh,
    const float* __restrict__ hc, float* __restrict__ hnout,  // [k][b]
    float* __restrict__ seq_base, int t,  // if: seq_base[(b*SS+t)*HH + h]
    float* __restrict__ cat_t,            // if: cat_t[b*H2 + h]
    float* __restrict__ d1) {             // if: d1[b*HH + h]
    const int b = tid & 31;
    const int h = c0 + (tid >> 5) * 4;
    float4 hr = ld4(bhh + h);
    float4 hz = ld4(bhh + HH + h);
    float4 hn = ld4(bhh + 2 * HH + h);
#pragma unroll
    for (int j = 0; j < NSPLIT; j++) {
        const float* P = partH + (size_t)j * PARTSZ + (size_t)b * H3 + h;
        hr = add4(hr, ld4(P));
        hz = add4(hz, ld4(P + HH));
        hn = add4(hn, ld4(P + 2 * HH));
    }
    float4 gr = make_float4(0.f, 0.f, 0.f, 0.f);
    float4 gz = gr, gn = gr;
    if (gi_slab) {
        const float* G = gi_slab + (size_t)b * H3 + h;
        gr = ld4(G);
        gz = ld4(G + HH);
        gn = ld4(G + 2 * HH);
    }
    if (gi_vec) {
        gr = add4(gr, ld4(gi_vec + h));
        gz = add4(gz, ld4(gi_vec + HH + h));
        gn = add4(gn, ld4(gi_vec + 2 * HH + h));
    }
    if (partX) {
#pragma unroll
        for (int j = 0; j < NSPLIT; j++) {
            const float* P = partX + (size_t)j * PARTSZ + (size_t)b * H3 + h;
            gr = add4(gr, ld4(P));
            gz = add4(gz, ld4(P + HH));
            gn = add4(gn, ld4(P + 2 * HH));
        }
    }
    float grr[4] = {gr.x, gr.y, gr.z, gr.w};
    float gzz[4] = {gz.x, gz.y, gz.z, gz.w};
    float gnn[4] = {gn.x, gn.y, gn.z, gn.w};
    float hrr[4] = {hr.x, hr.y, hr.z, hr.w};
    float hzz[4] = {hz.x, hz.y, hz.z, hz.w};
    float hnn[4] = {hn.x, hn.y, hn.z, hn.w};
#pragma unroll
    for (int i = 0; i < 4; i++) {
        float r = 1.f / (1.f + expf(-(grr[i] + hrr[i])));
        float z = 1.f / (1.f + expf(-(gzz[i] + hzz[i])));
        float n = tanhf(gnn[i] + r * hnn[i]);
        float hp = hc[(size_t)(h + i) * 32 + b];
        float out = (1.f - z) * n + z * hp;
        hnout[(size_t)(h + i) * 32 + b] = out;
        if (seq_base) seq_base[((size_t)b * SS + t) * HH + h + i] = out;
        if (cat_t) cat_t[(size_t)b * H2 + h + i] = out;
        if (d1) d1[(size_t)b * HH + h + i] = out;
    }
}

// winner check: bump per-bundle counter; true for the block seeing the final arrival
__device__ __forceinline__ bool winner_check(int* cnt_cell, int thresh, int tid, int* s_win) {
    __syncthreads();   // partial stores done
    if (tid == 0) {
        __threadfence();
        int old = atomicAdd(cnt_cell, 1);
        *s_win = (old == thresh - 1);
        if (*s_win) __threadfence();
    }
    __syncthreads();
    return *s_win != 0;
}

// ---------------- encoder fused step: rec partial + winner gate (one launch/step) ----------------
__global__ void __launch_bounds__(256)
enc_step(const float* __restrict__ gi_t,  // [b][n] slab for this step
         const float* __restrict__ wt, const float* __restrict__ bhh,
         const float* __restrict__ hc, float* __restrict__ hn,
         float* __restrict__ seq, int t,
         float* __restrict__ d1_or_null,
         float* __restrict__ part, int* __restrict__ cnt, int thresh) {
    __shared__ float sA[KC * 32];
    __shared__ int s_win;
    const int tid = threadIdx.x;
    const int nb = blockIdx.x & 31;
    const int ks = blockIdx.x >> 5;
    const int c0 = nb * 32;
    rec_partial(hc, wt, part + (size_t)ks * PARTSZ, sA, tid, c0, ks * KC);
    if (winner_check(&cnt[nb], thresh, tid, &s_win))
        gate_bundle(tid, c0, part, nullptr, gi_t, nullptr, bhh,
                    hc, hn, seq, t, nullptr, d1_or_null);
}

// ---------------- decoder K2: 3 matmul sides + winner gate for layer 0 ----------------
__global__ void __launch_bounds__(256)
dec_k2(const float* __restrict__ h0c, const float* __restrict__ ctxt,
       const float* __restrict__ h1c,
       const float* __restrict__ whh0t, const float* __restrict__ wih0ct,
       const float* __restrict__ whh1t,
       const float* __restrict__ epre_t, const float* __restrict__ bhh0,
       float* __restrict__ h0n,
       float* __restrict__ part, int* __restrict__ cnt0, int* __restrict__ cnt1,
       int thresh) {
    __shared__ float sA[KC * 32];
    __shared__ int s_win;
    const int tid = threadIdx.x;
    const int side = blockIdx.x >> 8;
    const int lb = blockIdx.x & 255;
    const int nb = lb & 31;
    const int ks = lb >> 5;
    const int c0 = nb * 32;
    const float* A = (side == 0) ? h0c : (side == 1) ? ctxt : h1c;
    const float* W = (side == 0) ? whh0t : (side == 1) ? wih0ct : whh1t;
    rec_partial(A, W, part + (size_t)(side * NSPLIT + ks) * PARTSZ, sA, tid, c0, ks * KC);
    if (side < 2) {
        if (winner_check(&cnt0[nb], thresh, tid, &s_win))
            gate_bundle(tid, c0, part, part + (size_t)NSPLIT * PARTSZ,
                        epre_t, nullptr, bhh0, h0c, h0n,
                        nullptr, 0, nullptr, nullptr);
    } else {
        __syncthreads();
        if (tid == 0) {
            __threadfence();
            atomicAdd(&cnt1[nb], 1);
        }
    }
}

// ---------------- decoder K3: x-side of layer 1 + winner gate for layer 1 ----------------
__global__ void __launch_bounds__(256)
dec_k3(const float* __restrict__ h0n, const float* __restrict__ wih1t,
       const float* __restrict__ h1c, const float* __restrict__ bih1,
       const float* __restrict__ bhh1,
       float* __restrict__ h1n, float* __restrict__ cat_t, float* __restrict__ d1row,
       float* __restrict__ part, int* __restrict__ cnt1, int thresh) {
    __shared__ float sA[KC * 32];
    __shared__ int s_win;
    const int tid = threadIdx.x;
    const int nb = blockIdx.x & 31;
    const int ks = blockIdx.x >> 5;
    const int c0 = nb * 32;
    rec_partial(h0n, wih1t, part + (size_t)(3 * NSPLIT + ks) * PARTSZ, sA, tid, c0, ks * KC);
    if (winner_check(&cnt1[nb], thresh, tid, &s_win))
        gate_bundle(tid, c0, part + (size_t)2 * NSPLIT * PARTSZ,
                    part + (size_t)3 * NSPLIT * PARTSZ,
                    nullptr, bih1, bhh1, h1c, h1n,
                    nullptr, 0, cat_t, d1row);
}

// ---------------- attention ----------------
__global__ void __launch_bounds__(256)
attn_kernel(const float* __restrict__ proj,
            const float* __restrict__ encout,
            const float* __restrict__ d1row,
            const int* __restrict__ src_ids,
            float* __restrict__ ctxt,           // [k][b]
            float* __restrict__ catrow) {       // + b*H2 + HH + h
    int b = blockIdx.x;
    __shared__ float sc[SS];
    int tid = threadIdx.x;
    int lane = tid & 31;
    int warp = tid >> 5;
    const float* d1b = d1row + (size_t)b * HH;

    for (int s = warp; s < SS; s += 8) {
        const float* pr = proj + ((size_t)b * SS + s) * HH;
        float p = 0.f;
#pragma unroll
        for (int j = 0; j < 8; j++) {
            int k0 = j * 128 + lane * 4;
            float4 dv = ld4(d1b + k0);
            float4 pv = ld4(pr + k0);
            p += dv.x * pv.x + dv.y * pv.y + dv.z * pv.z + dv.w * pv.w;
        }
#pragma unroll
        for (int o = 16; o; o >>= 1) p += __shfl_xor_sync(0xffffffffu, p, o);
        if (lane == 0) sc[s] = (src_ids[b * SS + s] != 0) ? p : -1e9f;
    }
    __syncthreads();
    if (warp == 0) {
        float v0 = sc[lane], v1 = sc[lane + 32];
        float m = fmaxf(v0, v1);
#pragma unroll
        for (int o = 16; o; o >>= 1) m = fmaxf(m, __shfl_xor_sync(0xffffffffu, m, o));
        float e0 = expf(v0 - m), e1 = expf(v1 - m);
        float su = e0 + e1;
#pragma unroll
        for (int o = 16; o; o >>= 1) su += __shfl_xor_sync(0xffffffffu, su, o);
        sc[lane] = e0 / su;
        sc[lane + 32] = e1 / su;
    }
    __syncthreads();
    for (int h = tid; h < HH; h += 256) {
        const float* eb = encout + (size_t)b * SS * HH + h;
        float a = 0.f;
#pragma unroll 8
        for (int s = 0; s < SS; s++) a += sc[s] * eb[(size_t)s * HH];
        ctxt[(size_t)h * 32 + b] = a;
        catrow[(size_t)b * H2 + HH + h] = a;
    }
}

// ---------------- host launcher ----------------
extern "C" void kernel_launch(void* const* d_in, const int* in_sizes, int n_in,
                              void* d_out, int out_size) {
    const int*   src_ids  = (const int*)d_in[0];
    const int*   tgt_ids  = (const int*)d_in[2];
    const float* enc_emb  = (const float*)d_in[3];
    const float* dec_emb  = (const float*)d_in[4];
    const float* enc_wih0 = (const float*)d_in[5];
    const float* enc_whh0 = (const float*)d_in[6];
    const float* enc_bih0 = (const float*)d_in[7];
    const float* enc_bhh0 = (const float*)d_in[8];
    const float* enc_wih1 = (const float*)d_in[9];
    const float* enc_whh1 = (const float*)d_in[10];
    const float* enc_bih1 = (const float*)d_in[11];
    const float* enc_bhh1 = (const float*)d_in[12];
    const float* dec_wih0 = (const float*)d_in[13];
    const float* dec_whh0 = (const float*)d_in[14];
    const float* dec_bih0 = (const float*)d_in[15];
    const float* dec_bhh0 = (const float*)d_in[16];
    const float* dec_wih1 = (const float*)d_in[17];
    const float* dec_whh1 = (const float*)d_in[18];
    const float* dec_bih1 = (const float*)d_in[19];
    const float* dec_bhh1 = (const float*)d_in[20];
    const float* attn_w   = (const float*)d_in[21];
    const float* out_w    = (const float*)d_in[22];
    const float* out_b    = (const float*)d_in[23];
    float* out = (float*)d_out;

    float* base = nullptr;
    cudaGetSymbolAddress((void**)&base, g_scratch);
    float* embS   = base + OFF_EMBS;
    float* gi0    = base + OFF_GI0;
    float* h0seq  = base + OFF_H0SEQ;
    float* gi1    = base + OFF_GI1;
    float* encout = base + OFF_ENCOUT;
    float* proj   = base + OFF_PROJ;
    float* embT   = base + OFF_EMBT;
    float* epre   = base + OFF_EPRE;
    float* cat    = base + OFF_CAT;
    float* h0A    = base + OFF_H0A;
    float* h0B    = base + OFF_H0B;
    float* h1A    = base + OFF_H1A;
    float* h1B    = base + OFF_H1B;
    float* ctxt   = base + OFF_CTXT;
    float* d1row  = base + OFF_D1ROW;
    float* part   = base + OFF_PART;
    int*   cnt    = (int*)(base + OFF_CNT);
    float* wt_ewhh0  = base + OFF_WT + 0 * WT_SZ;
    float* wt_ewhh1  = base + OFF_WT + 1 * WT_SZ;
    float* wt_dwhh0  = base + OFF_WT + 2 * WT_SZ;
    float* wt_dwhh1  = base + OFF_WT + 3 * WT_SZ;
    float* wt_dwih0c = base + OFF_WT + 4 * WT_SZ;
    float* wt_dwih1  = base + OFF_WT + 5 * WT_SZ;

    cudaFuncSetAttribute(gemm_final, cudaFuncAttributeMaxDynamicSharedMemorySize, FSM_BYTES);

    dim3 tgrid(H3 / 32, HH / 32);
    transpose_w<<<tgrid, 256>>>(enc_whh0, HH, 0, wt_ewhh0);
    transpose_w<<<tgrid, 256>>>(enc_whh1, HH, 0, wt_ewhh1);
    transpose_w<<<tgrid, 256>>>(dec_whh0, HH, 0, wt_dwhh0);
    transpose_w<<<tgrid, 256>>>(dec_whh1, HH, 0, wt_dwhh1);
    transpose_w<<<tgrid, 256>>>(dec_wih0, EE + HH, EE, wt_dwih0c);
    transpose_w<<<tgrid, 256>>>(dec_wih1, HH, 0, wt_dwih1);

    // ---- encoder ----
    embed_enc_kernel<<<(BB * SS * EE + 255) / 256, 256>>>(src_ids, enc_emb, embS);
    gemm_tf32<MODE_TENC><<<dim3(H3 / 128, 16), 256>>>(
        embS, EE, enc_wih0, EE, enc_bih0, gi0, BB * SS, H3, EE);
    // zero states (h0A..h1B contiguous) + counters
    zero_kernel<<<(4 * BB * HH + 255) / 256, 256>>>(h0A, 4 * BB * HH);
    zero_kernel<<<1, 128>>>(base + OFF_CNT, 128);

    float* h0_cur = h0A; float* h0_nxt = h0B;
    float* h1_cur = h1A; float* h1_nxt = h1B;

    // layer-0 scan: 1 fused launch per step
    for (int t = 0; t < SS; t++) {
        enc_step<<<256, 256>>>(gi0 + (size_t)t * BB * H3, wt_ewhh0, enc_bhh0,
                               h0_cur, h0_nxt, h0seq, t, nullptr,
                               part, cnt, (t + 1) * NSPLIT);
        float* tmp = h0_cur; h0_cur = h0_nxt; h0_nxt = tmp;
    }
    gemm_tf32<MODE_TENC><<<dim3(H3 / 128, 16), 256>>>(
        h0seq, HH, enc_wih1, HH, enc_bih1, gi1, BB * SS, H3, HH);
    // layer-1 scan
    for (int t = 0; t < SS; t++) {
        enc_step<<<256, 256>>>(gi1 + (size_t)t * BB * H3, wt_ewhh1, enc_bhh1,
                               h1_cur, h1_nxt, encout, t,
                               (t == SS - 1) ? d1row : nullptr,
                               part, cnt + 32, (t + 1) * NSPLIT);
        float* tmp = h1_cur; h1_cur = h1_nxt; h1_nxt = tmp;
    }

    gemm_tf32<MODE_NORM><<<dim3(HH / 128, 16), 256>>>(
        encout, HH, attn_w, HH, nullptr, proj, BB * SS, HH, HH);

    // ---- decoder pre ----
    embed_dec_kernel<<<(TM * BB * EE + 255) / 256, 256>>>(tgt_ids, dec_emb, embT);
    gemm_tf32<MODE_TDEC><<<dim3(H3 / 128, (TM * BB + 127) / 128), 256>>>(
        embT, EE, dec_wih0, EE + HH, dec_bih0, epre, TM * BB, H3, EE);

    // ---- decoder loop: 3 launches per step ----
    for (int t = 0; t < TM; t++) {
        float* epre_t = epre + (size_t)t * BB * H3;
        float* cat_t  = cat + (size_t)t * BB * H2;
        attn_kernel<<<BB, 256>>>(proj, encout, d1row, src_ids, ctxt, cat_t);
        dec_k2<<<3 * 256, 256>>>(h0_cur, ctxt, h1_cur,
                                 wt_dwhh0, wt_dwih0c, wt_dwhh1,
                                 epre_t, dec_bhh0, h0_nxt,
                                 part, cnt + 64, cnt + 96, (t + 1) * 2 * NSPLIT);
        dec_k3<<<256, 256>>>(h0_nxt, wt_dwih1, h1_cur, dec_bih1, dec_bhh1,
                             h1_nxt, cat_t, d1row,
                             part, cnt + 96, (t + 1) * 2 * NSPLIT);
        float* tmp;
        tmp = h0_cur; h0_cur = h0_nxt; h0_nxt = tmp;
        tmp = h1_cur; h1_cur = h1_nxt; h1_nxt = tmp;
    }

    // ---- final projection: logits = cat @ out_w^T + out_b -> (B, TM, V) ----
    gemm_final<<<dim3((TM * BB + 127) / 128, VV / 256), 256, FSM_BYTES>>>(
        cat, H2, out_w, H2, out_b, out, TM * BB, VV, H2);
}

// round 7
// speedup vs baseline: 1.8054x; 1.8054x over previous
#include <cuda_runtime.h>
#include <cstdint>

// Problem dims
#define BB 32
#define SS 64
#define TT 48
#define TM 47      // T-1 decoder steps
#define VV 32000
#define EE 512
#define HH 1024
#define H3 3072
#define H2 2048
#define KSPLIT 4
#define PARTSZ ((size_t)BB * H3)

// ---------------- scratch (device global, no allocs) ----------------
#define OFF_EMBS   0ull                                   // B*S*E
#define OFF_GI0    (OFF_EMBS   + (size_t)BB*SS*EE)        // [t][n][b] slabs
#define OFF_H0SEQ  (OFF_GI0    + (size_t)BB*SS*H3)        // [b][t][h]
#define OFF_GI1    (OFF_H0SEQ  + (size_t)BB*SS*HH)        // [t][n][b]
#define OFF_ENCOUT (OFF_GI1    + (size_t)BB*SS*H3)        // [b][t][h]
#define OFF_PROJ   (OFF_ENCOUT + (size_t)BB*SS*HH)        // [b][s][h]
#define OFF_EMBT   (OFF_PROJ   + (size_t)BB*SS*HH)        // rows m=t*B+b
#define OFF_EPRE   (OFF_EMBT   + (size_t)TM*BB*EE)        // [t][n][b] slabs
#define OFF_CAT    (OFF_EPRE   + (size_t)TM*BB*H3)        // rows m=t*B+b, [d1|ctx]
#define OFF_H0A    (OFF_CAT    + (size_t)TM*BB*H2)        // state [k][b]
#define OFF_H0B    (OFF_H0A    + (size_t)BB*HH)
#define OFF_H1A    (OFF_H0B    + (size_t)BB*HH)
#define OFF_H1B    (OFF_H1A    + (size_t)BB*HH)
#define OFF_CTXT   (OFF_H1B    + (size_t)BB*HH)           // ctx [k][b]
#define OFF_D1ROW  (OFF_CTXT   + (size_t)BB*HH)           // d1 [b][h]
#define OFF_PART   (OFF_D1ROW  + (size_t)BB*HH)           // 8 partial slabs [n][b]
#define OFF_WT     (OFF_PART   + 8*PARTSZ)                // 6 transposed weights [k][n]
#define WT_SZ      ((size_t)HH * H3)
#define SCRATCH_TOTAL (OFF_WT + 6*WT_SZ)

__device__ float g_scratch[SCRATCH_TOTAL];

// ---------------- small helpers ----------------
__device__ __forceinline__ float4 ld4(const float* p) {
    return *reinterpret_cast<const float4*>(p);
}
__device__ __forceinline__ void st4(float* p, float4 v) {
    *reinterpret_cast<float4*>(p) = v;
}

__global__ void zero_kernel(float* p, int n) {
    int i = blockIdx.x * blockDim.x + threadIdx.x;
    if (i < n) p[i] = 0.f;
}

__global__ void embed_enc_kernel(const int* __restrict__ ids,
                                 const float* __restrict__ table,
                                 float* __restrict__ out) {
    int i = blockIdx.x * blockDim.x + threadIdx.x;
    if (i >= BB * SS * EE) return;
    int tok = i / EE;
    int e = i % EE;
    out[i] = table[(size_t)ids[tok] * EE + e];
}

__global__ void embed_dec_kernel(const int* __restrict__ tgt,
                                 const float* __restrict__ table,
                                 float* __restrict__ out) {
    int i = blockIdx.x * blockDim.x + threadIdx.x;
    if (i >= TM * BB * EE) return;
    int m = i / EE;
    int e = i % EE;
    int t = m / BB;
    int b = m % BB;
    out[i] = table[(size_t)tgt[b * TT + t] * EE + e];
}

// one launch transposes all 6 recurrent weight matrices: Wt[k][n] = W[n][koff+k]
__global__ void transpose_all(const float* __restrict__ w0, const float* __restrict__ w1,
                              const float* __restrict__ w2, const float* __restrict__ w3,
                              const float* __restrict__ w4, const float* __restrict__ w5,
                              float* __restrict__ wt_base) {
    __shared__ float s[32][33];
    const int z = blockIdx.z;
    const float* W = (z == 0) ? w0 : (z == 1) ? w1 : (z == 2) ? w2
                   : (z == 3) ? w3 : (z == 4) ? w4 : w5;
    const int ldw = (z == 4) ? (EE + HH) : HH;
    const int koff = (z == 4) ? EE : 0;
    float* Wt = wt_base + (size_t)z * WT_SZ;
    int n0 = blockIdx.x * 32, k0 = blockIdx.y * 32;
    int tx = threadIdx.x & 31, ty = threadIdx.x >> 5;
#pragma unroll
    for (int i = 0; i < 4; i++)
        s[ty + i * 8][tx] = W[(size_t)(n0 + ty + i * 8) * ldw + koff + k0 + tx];
    __syncthreads();
#pragma unroll
    for (int i = 0; i < 4; i++)
        Wt[(size_t)(k0 + ty + i * 8) * H3 + n0 + tx] = s[tx][ty + i * 8];
}

// ---------------- tf32 helpers ----------------
__device__ __forceinline__ uint32_t f2tf(float f) {
    uint32_t u;
    asm("cvt.rna.tf32.f32 %0, %1;" : "=r"(u) : "f"(f));
    return u;
}

// ---------------- tf32 GEMM (batched projections; 128x128, 4 warps) ----------------
#define MODE_NORM 0
#define MODE_TENC 2   // m = b*64+t -> [t][n][b] slabs
#define MODE_TDEC 3   // m = t*32+b -> [t][n][b] slabs

template <int MODE>
__global__ void __launch_bounds__(256)
gemm_tf32(const float* __restrict__ A, int lda,
          const float* __restrict__ W, int ldw,
          const float* __restrict__ bias,
          float* __restrict__ C, int M, int N, int K) {
    __shared__ uint32_t As[32][132];   // [k][m]
    __shared__ uint32_t Ws[32][132];   // [k][n]
    const int bm = blockIdx.y * 128, bn = blockIdx.x * 128;
    const int tid = threadIdx.x;
    const int warp = tid >> 5, lane = tid & 31;
    const int wm = (warp & 1) * 64, wn = (warp >> 1) * 32;
    const int g = lane >> 2, tig = lane & 3;

    float acc[4][4][4];
#pragma unroll
    for (int a = 0; a < 4; a++)
#pragma unroll
        for (int b = 0; b < 4; b++)
#pragma unroll
            for (int c = 0; c < 4; c++) acc[a][b][c] = 0.f;

    float4 pa[4], pw[4];
#pragma unroll
    for (int i = 0; i < 4; i++) {
        int e = tid + i * 256;
        int m = e >> 3, kq = (e & 7) * 4;
        float4 v = make_float4(0.f, 0.f, 0.f, 0.f);
        if (bm + m < M) v = ld4(A + (size_t)(bm + m) * lda + kq);
        pa[i] = v;
        pw[i] = ld4(W + (size_t)(bn + m) * ldw + kq);
    }
#pragma unroll
    for (int i = 0; i < 4; i++) {
        int e = tid + i * 256;
        int m = e >> 3, kq = (e & 7) * 4;
        As[kq + 0][m] = f2tf(pa[i].x); As[kq + 1][m] = f2tf(pa[i].y);
        As[kq + 2][m] = f2tf(pa[i].z); As[kq + 3][m] = f2tf(pa[i].w);
        Ws[kq + 0][m] = f2tf(pw[i].x); Ws[kq + 1][m] = f2tf(pw[i].y);
        Ws[kq + 2][m] = f2tf(pw[i].z); Ws[kq + 3][m] = f2tf(pw[i].w);
    }
    __syncthreads();

    for (int k0 = 0; k0 < K; k0 += 32) {
        bool has_next = (k0 + 32) < K;
        if (has_next) {
#pragma unroll
            for (int i = 0; i < 4; i++) {
                int e = tid + i * 256;
                int m = e >> 3, kq = (e & 7) * 4;
                float4 v = make_float4(0.f, 0.f, 0.f, 0.f);
                if (bm + m < M) v = ld4(A + (size_t)(bm + m) * lda + k0 + 32 + kq);
                pa[i] = v;
                pw[i] = ld4(W + (size_t)(bn + m) * ldw + k0 + 32 + kq);
            }
        }
#pragma unroll
        for (int kk = 0; kk < 32; kk += 8) {
            uint32_t af[4][4];
#pragma unroll
            for (int mt = 0; mt < 4; mt++) {
                int ml = wm + mt * 16 + g;
                af[mt][0] = As[kk + tig][ml];
                af[mt][1] = As[kk + tig][ml + 8];
                af[mt][2] = As[kk + tig + 4][ml];
                af[mt][3] = As[kk + tig + 4][ml + 8];
            }
            uint32_t bf[4][2];
#pragma unroll
            for (int nt = 0; nt < 4; nt++) {
                int nl = wn + nt * 8 + g;
                bf[nt][0] = Ws[kk + tig][nl];
                bf[nt][1] = Ws[kk + tig + 4][nl];
            }
#pragma unroll
            for (int mt = 0; mt < 4; mt++)
#pragma unroll
                for (int nt = 0; nt < 4; nt++) {
                    asm volatile(
                        "mma.sync.aligned.m16n8k8.row.col.f32.tf32.tf32.f32 "
                        "{%0,%1,%2,%3}, {%4,%5,%6,%7}, {%8,%9}, {%0,%1,%2,%3};\n"
                        : "+f"(acc[mt][nt][0]), "+f"(acc[mt][nt][1]),
                          "+f"(acc[mt][nt][2]), "+f"(acc[mt][nt][3])
                        : "r"(af[mt][0]), "r"(af[mt][1]), "r"(af[mt][2]), "r"(af[mt][3]),
                          "r"(bf[nt][0]), "r"(bf[nt][1]));
                }
        }
        __syncthreads();
        if (has_next) {
#pragma unroll
            for (int i = 0; i < 4; i++) {
                int e = tid + i * 256;
                int m = e >> 3, kq = (e & 7) * 4;
                As[kq + 0][m] = f2tf(pa[i].x); As[kq + 1][m] = f2tf(pa[i].y);
                As[kq + 2][m] = f2tf(pa[i].z); As[kq + 3][m] = f2tf(pa[i].w);
                Ws[kq + 0][m] = f2tf(pw[i].x); Ws[kq + 1][m] = f2tf(pw[i].y);
                Ws[kq + 2][m] = f2tf(pw[i].z); Ws[kq + 3][m] = f2tf(pw[i].w);
            }
            __syncthreads();
        }
    }

#pragma unroll
    for (int mt = 0; mt < 4; mt++) {
#pragma unroll
        for (int i2 = 0; i2 < 2; i2++) {
            int m = bm + wm + mt * 16 + g + i2 * 8;
            if (m >= M) continue;
#pragma unroll
            for (int nt = 0; nt < 4; nt++) {
#pragma unroll
                for (int j = 0; j < 2; j++) {
                    int n = bn + wn + nt * 8 + tig * 2 + j;
                    float v = acc[mt][nt][i2 * 2 + j];
                    if (bias) v += bias[n];
                    if (MODE == MODE_NORM) {
                        C[(size_t)m * N + n] = v;
                    } else if (MODE == MODE_TENC) {
                        int t = m & 63, b = m >> 6;
                        C[((size_t)t * H3 + n) * 32 + b] = v;
                    } else {  // MODE_TDEC
                        int t = m >> 5, b = m & 31;
                        C[((size_t)t * H3 + n) * 32 + b] = v;
                    }
                }
            }
        }
    }
}

// ---------------- final projection: 128x256 tile, 8 warps, m-major grid ----------------
#define FSM_WORDS (128 * 36 + 256 * 36)
#define FSM_BYTES (FSM_WORDS * 4)

__global__ void __launch_bounds__(256)
gemm_final(const float* __restrict__ A, int lda,
           const float* __restrict__ W, int ldw,
           const float* __restrict__ bias,
           float* __restrict__ C, int M, int N, int K) {
    extern __shared__ uint32_t sm[];
    uint32_t* As = sm;               // [128][36]
    uint32_t* Ws = sm + 128 * 36;    // [256][36]
    const int bm = blockIdx.x * 128;   // m-major: W streams from DRAM once
    const int bn = blockIdx.y * 256;
    const int tid = threadIdx.x;
    const int warp = tid >> 5, lane = tid & 31;
    const int wm = (warp & 1) * 64, wn = (warp >> 1) * 64;
    const int g = lane >> 2, tig = lane & 3;

    float acc[4][8][4];
#pragma unroll
    for (int a = 0; a < 4; a++)
#pragma unroll
        for (int b = 0; b < 8; b++)
#pragma unroll
            for (int c = 0; c < 4; c++) acc[a][b][c] = 0.f;

    const int kq = (tid & 7) * 4;
    float4 pa[4], pw[8];

#define LDA_CHUNK(K0)                                                        \
    _Pragma("unroll") for (int i = 0; i < 4; i++) {                          \
        int e = tid + i * 256;                                               \
        int m = e >> 3;                                                      \
        float4 v = make_float4(0.f, 0.f, 0.f, 0.f);                          \
        if (bm + m < M) v = ld4(A + (size_t)(bm + m) * lda + (K0) + kq);     \
        pa[i] = v;                                                           \
    }
#define LDW_CHUNK(K0)                                                        \
    _Pragma("unroll") for (int i = 0; i < 8; i++) {                          \
        int e = tid + i * 256;                                               \
        int n = e >> 3;                                                      \
        pw[i] = ld4(W + (size_t)(bn + n) * ldw + (K0) + kq);                 \
    }
#define ST_CHUNK()                                                           \
    _Pragma("unroll") for (int i = 0; i < 4; i++) {                          \
        int e = tid + i * 256;                                               \
        int m = e >> 3;                                                      \
        uint4 u = make_uint4(f2tf(pa[i].x), f2tf(pa[i].y),                   \
                             f2tf(pa[i].z), f2tf(pa[i].w));                  \
        *reinterpret_cast<uint4*>(&As[m * 36 + kq]) = u;                     \
    }                                                                        \
    _Pragma("unroll") for (int i = 0; i < 8; i++) {                          \
        int e = tid + i * 256;                                               \
        int n = e >> 3;                                                      \
        uint4 u = make_uint4(f2tf(pw[i].x), f2tf(pw[i].y),                   \
                             f2tf(pw[i].z), f2tf(pw[i].w));                  \
        *reinterpret_cast<uint4*>(&Ws[n * 36 + kq]) = u;                     \
    }

    LDA_CHUNK(0)
    LDW_CHUNK(0)
    ST_CHUNK()
    __syncthreads();

    for (int k0 = 0; k0 < K; k0 += 32) {
        bool has_next = (k0 + 32) < K;
        if (has_next) {
            LDA_CHUNK(k0 + 32)
            LDW_CHUNK(k0 + 32)
        }
#pragma unroll
        for (int kk = 0; kk < 32; kk += 8) {
            uint32_t af[4][4];
#pragma unroll
            for (int mt = 0; mt < 4; mt++) {
                int ml = wm + mt * 16 + g;
                af[mt][0] = As[ml * 36 + kk + tig];
                af[mt][1] = As[(ml + 8) * 36 + kk + tig];
                af[mt][2] = As[ml * 36 + kk + tig + 4];
                af[mt][3] = As[(ml + 8) * 36 + kk + tig + 4];
            }
            uint32_t bf[8][2];
#pragma unroll
            for (int nt = 0; nt < 8; nt++) {
                int nl = wn + nt * 8 + g;
                bf[nt][0] = Ws[nl * 36 + kk + tig];
                bf[nt][1] = Ws[nl * 36 + kk + tig + 4];
            }
#pragma unroll
            for (int mt = 0; mt < 4; mt++)
#pragma unroll
                for (int nt = 0; nt < 8; nt++) {
                    asm volatile(
                        "mma.sync.aligned.m16n8k8.row.col.f32.tf32.tf32.f32 "
                        "{%0,%1,%2,%3}, {%4,%5,%6,%7}, {%8,%9}, {%0,%1,%2,%3};\n"
                        : "+f"(acc[mt][nt][0]), "+f"(acc[mt][nt][1]),
                          "+f"(acc[mt][nt][2]), "+f"(acc[mt][nt][3])
                        : "r"(af[mt][0]), "r"(af[mt][1]), "r"(af[mt][2]), "r"(af[mt][3]),
                          "r"(bf[nt][0]), "r"(bf[nt][1]));
                }
        }
        __syncthreads();
        if (has_next) {
            ST_CHUNK()
            __syncthreads();
        }
    }

    // epilogue: rows m = t*32+b -> out row b*TM + t
#pragma unroll
    for (int mt = 0; mt < 4; mt++) {
#pragma unroll
        for (int i2 = 0; i2 < 2; i2++) {
            int m = bm + wm + mt * 16 + g + i2 * 8;
            if (m >= M) continue;
            int b = m & 31, t = m >> 5;
            float* cr = C + (size_t)(b * TM + t) * N;
#pragma unroll
            for (int nt = 0; nt < 8; nt++) {
#pragma unroll
                for (int j = 0; j < 2; j++) {
                    int n = bn + wn + nt * 8 + tig * 2 + j;
                    cr[n] = acc[mt][nt][i2 * 2 + j] + bias[n];
                }
            }
        }
    }
#undef LDA_CHUNK
#undef LDW_CHUNK
#undef ST_CHUNK
}

// ---------------- recurrent small GEMM (round-4 proven) ----------------
// A [k][b] (stride 32), Wt [k][n] (stride H3). grid (H3/64, KSPLIT, nmat).
// Writes part[(z*KSPLIT+y)] in [n][b] layout.
__global__ void __launch_bounds__(256)
rec_gemm(const float* __restrict__ A0, const float* __restrict__ W0,
         const float* __restrict__ A1, const float* __restrict__ W1,
         float* __restrict__ part) {
    const float* At = blockIdx.z ? A1 : A0;
    const float* Wt = blockIdx.z ? W1 : W0;
    __shared__ float sA[256 * 32];
    const int n0 = blockIdx.x * 64;
    const int k0 = blockIdx.y * (HH / KSPLIT);   // 256 k per split
    const int tid = threadIdx.x;

    const float4* src = reinterpret_cast<const float4*>(At + (size_t)k0 * 32);
#pragma unroll
    for (int i = 0; i < 8; i++)
        reinterpret_cast<float4*>(sA)[tid + i * 256] = src[tid + i * 256];
    __syncthreads();

    const int nq = (tid & 15) * 4;
    const int b0 = (tid >> 4) * 2;
    float4 acc0 = make_float4(0.f, 0.f, 0.f, 0.f);
    float4 acc1 = make_float4(0.f, 0.f, 0.f, 0.f);
    const float* wp = Wt + (size_t)k0 * H3 + n0 + nq;
#pragma unroll 4
    for (int k = 0; k < HH / KSPLIT; k++) {
        float4 w = ld4(wp + (size_t)k * H3);
        float a0 = sA[k * 32 + b0];
        float a1 = sA[k * 32 + b0 + 1];
        acc0.x += a0 * w.x; acc0.y += a0 * w.y; acc0.z += a0 * w.z; acc0.w += a0 * w.w;
        acc1.x += a1 * w.x; acc1.y += a1 * w.y; acc1.z += a1 * w.z; acc1.w += a1 * w.w;
    }
    float* P = part + (size_t)(blockIdx.z * KSPLIT + blockIdx.y) * PARTSZ;
    P[(size_t)(n0 + nq + 0) * 32 + b0] = acc0.x;
    P[(size_t)(n0 + nq + 1) * 32 + b0] = acc0.y;
    P[(size_t)(n0 + nq + 2) * 32 + b0] = acc0.z;
    P[(size_t)(n0 + nq + 3) * 32 + b0] = acc0.w;
    P[(size_t)(n0 + nq + 0) * 32 + b0 + 1] = acc1.x;
    P[(size_t)(n0 + nq + 1) * 32 + b0 + 1] = acc1.y;
    P[(size_t)(n0 + nq + 2) * 32 + b0 + 1] = acc1.z;
    P[(size_t)(n0 + nq + 3) * 32 + b0 + 1] = acc1.w;
}

// ---------------- GRU gate (round-4 proven) ----------------
__global__ void __launch_bounds__(256)
gru_gate(const float* __restrict__ partH,
         const float* __restrict__ partX,       // nullable
         const float* __restrict__ gi_slab,     // nullable [n][b] slab
         const float* __restrict__ gi_vec,      // nullable (bih)
         const float* __restrict__ bhh,
         const float* __restrict__ h_in,        // [k][b]
         float* __restrict__ h_out,             // [k][b]
         float* __restrict__ seq_row, int seq_stride,  // nullable, [b*stride + h]
         float* __restrict__ cat_row,           // nullable, + b*H2 + h
         float* __restrict__ d1row)             // nullable, [b*H + h]
{
    int idx = blockIdx.x * 256 + threadIdx.x;
    int b = idx & 31, h = idx >> 5;
    float gr = 0.f, gz = 0.f, gn = 0.f;
    if (gi_slab) {
        gr = gi_slab[(size_t)h * 32 + b];
        gz = gi_slab[(size_t)(HH + h) * 32 + b];
        gn = gi_slab[(size_t)(2 * HH + h) * 32 + b];
    }
    if (gi_vec) { gr += gi_vec[h]; gz += gi_vec[HH + h]; gn += gi_vec[2 * HH + h]; }
    float hr = bhh[h], hz = bhh[HH + h], hn = bhh[2 * HH + h];
#pragma unroll
    for (int j = 0; j < KSPLIT; j++) {
        const float* P = partH + (size_t)j * PARTSZ;
        hr += P[(size_t)h * 32 + b];
        hz += P[(size_t)(HH + h) * 32 + b];
        hn += P[(size_t)(2 * HH + h) * 32 + b];
    }
    if (partX) {
#pragma unroll
        for (int j = 0; j < KSPLIT; j++) {
            const float* P = partX + (size_t)j * PARTSZ;
            gr += P[(size_t)h * 32 + b];
            gz += P[(size_t)(HH + h) * 32 + b];
            gn += P[(size_t)(2 * HH + h) * 32 + b];
        }
    }
    float r = 1.f / (1.f + expf(-(gr + hr)));
    float z = 1.f / (1.f + expf(-(gz + hz)));
    float n = tanhf(gn + r * hn);
    float hp = h_in[(size_t)h * 32 + b];
    float out = (1.f - z) * n + z * hp;
    h_out[(size_t)h * 32 + b] = out;
    if (seq_row) seq_row[(size_t)b * seq_stride + h] = out;
    if (cat_row) cat_row[(size_t)b * H2 + h] = out;
    if (d1row) d1row[(size_t)b * HH + h] = out;
}

// ---------------- attention ----------------
__global__ void __launch_bounds__(256)
attn_kernel(const float* __restrict__ proj,
            const float* __restrict__ encout,
            const float* __restrict__ d1row,
            const int* __restrict__ src_ids,
            float* __restrict__ ctxt,           // [k][b]
            float* __restrict__ catrow) {       // + b*H2 + HH + h
    int b = blockIdx.x;
    __shared__ float sc[SS];
    int tid = threadIdx.x;
    int lane = tid & 31;
    int warp = tid >> 5;
    const float* d1b = d1row + (size_t)b * HH;

    for (int s = warp; s < SS; s += 8) {
        const float* pr = proj + ((size_t)b * SS + s) * HH;
        float p = 0.f;
#pragma unroll
        for (int j = 0; j < 8; j++) {
            int k0 = j * 128 + lane * 4;
            float4 dv = ld4(d1b + k0);
            float4 pv = ld4(pr + k0);
            p += dv.x * pv.x + dv.y * pv.y + dv.z * pv.z + dv.w * pv.w;
        }
#pragma unroll
        for (int o = 16; o; o >>= 1) p += __shfl_xor_sync(0xffffffffu, p, o);
        if (lane == 0) sc[s] = (src_ids[b * SS + s] != 0) ? p : -1e9f;
    }
    __syncthreads();
    if (warp == 0) {
        float v0 = sc[lane], v1 = sc[lane + 32];
        float m = fmaxf(v0, v1);
#pragma unroll
        for (int o = 16; o; o >>= 1) m = fmaxf(m, __shfl_xor_sync(0xffffffffu, m, o));
        float e0 = expf(v0 - m), e1 = expf(v1 - m);
        float su = e0 + e1;
#pragma unroll
        for (int o = 16; o; o >>= 1) su += __shfl_xor_sync(0xffffffffu, su, o);
        sc[lane] = e0 / su;
        sc[lane + 32] = e1 / su;
    }
    __syncthreads();
    for (int h = tid; h < HH; h += 256) {
        const float* eb = encout + (size_t)b * SS * HH + h;
        float a = 0.f;
#pragma unroll 8
        for (int s = 0; s < SS; s++) a += sc[s] * eb[(size_t)s * HH];
        ctxt[(size_t)h * 32 + b] = a;
        catrow[(size_t)b * H2 + HH + h] = a;
    }
}

// ---------------- host launcher ----------------
extern "C" void kernel_launch(void* const* d_in, const int* in_sizes, int n_in,
                              void* d_out, int out_size) {
    const int*   src_ids  = (const int*)d_in[0];
    const int*   tgt_ids  = (const int*)d_in[2];
    const float* enc_emb  = (const float*)d_in[3];
    const float* dec_emb  = (const float*)d_in[4];
    const float* enc_wih0 = (const float*)d_in[5];
    const float* enc_whh0 = (const float*)d_in[6];
    const float* enc_bih0 = (const float*)d_in[7];
    const float* enc_bhh0 = (const float*)d_in[8];
    const float* enc_wih1 = (const float*)d_in[9];
    const float* enc_whh1 = (const float*)d_in[10];
    const float* enc_bih1 = (const float*)d_in[11];
    const float* enc_bhh1 = (const float*)d_in[12];
    const float* dec_wih0 = (const float*)d_in[13];
    const float* dec_whh0 = (const float*)d_in[14];
    const float* dec_bih0 = (const float*)d_in[15];
    const float* dec_bhh0 = (const float*)d_in[16];
    const float* dec_wih1 = (const float*)d_in[17];
    const float* dec_whh1 = (const float*)d_in[18];
    const float* dec_bih1 = (const float*)d_in[19];
    const float* dec_bhh1 = (const float*)d_in[20];
    const float* attn_w   = (const float*)d_in[21];
    const float* out_w    = (const float*)d_in[22];
    const float* out_b    = (const float*)d_in[23];
    float* out = (float*)d_out;

    float* base = nullptr;
    cudaGetSymbolAddress((void**)&base, g_scratch);
    float* embS   = base + OFF_EMBS;
    float* gi0    = base + OFF_GI0;
    float* h0seq  = base + OFF_H0SEQ;
    float* gi1    = base + OFF_GI1;
    float* encout = base + OFF_ENCOUT;
    float* proj   = base + OFF_PROJ;
    float* embT   = base + OFF_EMBT;
    float* epre   = base + OFF_EPRE;
    float* cat    = base + OFF_CAT;
    float* h0A    = base + OFF_H0A;
    float* h0B    = base + OFF_H0B;
    float* h1A    = base + OFF_H1A;
    float* h1B    = base + OFF_H1B;
    float* ctxt   = base + OFF_CTXT;
    float* d1row  = base + OFF_D1ROW;
    float* part   = base + OFF_PART;
    float* wt_ewhh0  = base + OFF_WT + 0 * WT_SZ;
    float* wt_ewhh1  = base + OFF_WT + 1 * WT_SZ;
    float* wt_dwhh0  = base + OFF_WT + 2 * WT_SZ;
    float* wt_dwhh1  = base + OFF_WT + 3 * WT_SZ;
    float* wt_dwih0c = base + OFF_WT + 4 * WT_SZ;
    float* wt_dwih1  = base + OFF_WT + 5 * WT_SZ;

    cudaFuncSetAttribute(gemm_final, cudaFuncAttributeMaxDynamicSharedMemorySize, FSM_BYTES);

    // launch order chosen so ncu (-s 5) lands on the first rec_gemm
    transpose_all<<<dim3(H3 / 32, HH / 32, 6), 256>>>(
        enc_whh0, enc_whh1, dec_whh0, dec_whh1, dec_wih0, dec_wih1, base + OFF_WT);
    embed_enc_kernel<<<(BB * SS * EE + 255) / 256, 256>>>(src_ids, enc_emb, embS);
    embed_dec_kernel<<<(TM * BB * EE + 255) / 256, 256>>>(tgt_ids, dec_emb, embT);
    gemm_tf32<MODE_TENC><<<dim3(H3 / 128, 16), 256>>>(
        embS, EE, enc_wih0, EE, enc_bih0, gi0, BB * SS, H3, EE);
    zero_kernel<<<(4 * BB * HH + 255) / 256, 256>>>(h0A, 4 * BB * HH);

    float* h0_cur = h0A; float* h0_nxt = h0B;
    float* h1_cur = h1A; float* h1_nxt = h1B;

    // layer-0 scan
    for (int t = 0; t < SS; t++) {
        rec_gemm<<<dim3(H3 / 64, KSPLIT, 1), 256>>>(h0_cur, wt_ewhh0, nullptr, nullptr, part);
        gru_gate<<<BB * HH / 256, 256>>>(part, nullptr,
                                         gi0 + (size_t)t * H3 * 32, nullptr, enc_bhh0,
                                         h0_cur, h0_nxt,
                                         h0seq + (size_t)t * HH, SS * HH, nullptr, nullptr);
        float* tmp = h0_cur; h0_cur = h0_nxt; h0_nxt = tmp;
    }
    gemm_tf32<MODE_TENC><<<dim3(H3 / 128, 16), 256>>>(
        h0seq, HH, enc_wih1, HH, enc_bih1, gi1, BB * SS, H3, HH);
    // layer-1 scan
    for (int t = 0; t < SS; t++) {
        rec_gemm<<<dim3(H3 / 64, KSPLIT, 1), 256>>>(h1_cur, wt_ewhh1, nullptr, nullptr, part);
        gru_gate<<<BB * HH / 256, 256>>>(part, nullptr,
                                         gi1 + (size_t)t * H3 * 32, nullptr, enc_bhh1,
                                         h1_cur, h1_nxt,
                                         encout + (size_t)t * HH, SS * HH, nullptr,
                                         (t == SS - 1) ? d1row : nullptr);
        float* tmp = h1_cur; h1_cur = h1_nxt; h1_nxt = tmp;
    }
    // proj = encout @ attn_w^T
    gemm_tf32<MODE_NORM><<<dim3(HH / 128, 16), 256>>>(
        encout, HH, attn_w, HH, nullptr, proj, BB * SS, HH, HH);

    // epre = embT @ dec_wih0[:, :E]^T + dec_bih0
    gemm_tf32<MODE_TDEC><<<dim3(H3 / 128, (TM * BB + 127) / 128), 256>>>(
        embT, EE, dec_wih0, EE + HH, dec_bih0, epre, TM * BB, H3, EE);

    // ---- decoder loop (round-4 proven 5-launch structure) ----
    for (int t = 0; t < TM; t++) {
        float* epre_t = epre + (size_t)t * H3 * 32;
        float* cat_t  = cat + (size_t)t * BB * H2;
        attn_kernel<<<BB, 256>>>(proj, encout, d1row, src_ids, ctxt, cat_t);
        // layer 0: h-side (z=0) = h0 @ whh0^T ; x-side (z=1) = ctx @ wih0[:,E:]^T
        rec_gemm<<<dim3(H3 / 64, KSPLIT, 2), 256>>>(h0_cur, wt_dwhh0, ctxt, wt_dwih0c, part);
        gru_gate<<<BB * HH / 256, 256>>>(part, part + 4 * PARTSZ,
                                         epre_t, nullptr, dec_bhh0,
                                         h0_cur, h0_nxt, nullptr, 0, nullptr, nullptr);
        // layer 1: h-side = h1 @ whh1^T ; x-side = h0_new @ wih1^T
        rec_gemm<<<dim3(H3 / 64, KSPLIT, 2), 256>>>(h1_cur, wt_dwhh1, h0_nxt, wt_dwih1, part);
        gru_gate<<<BB * HH / 256, 256>>>(part, part + 4 * PARTSZ,
                                         nullptr, dec_bih1, dec_bhh1,
                                         h1_cur, h1_nxt, nullptr, 0, cat_t, d1row);
        float* tmp;
        tmp = h0_cur; h0_cur = h0_nxt; h0_nxt = tmp;
        tmp = h1_cur; h1_cur = h1_nxt; h1_nxt = tmp;
    }

    // ---- final projection: logits = cat @ out_w^T + out_b -> (B, TM, V) ----
    gemm_final<<<dim3((TM * BB + 127) / 128, VV / 256), 256, FSM_BYTES>>>(
        cat, H2, out_w, H2, out_b, out, TM * BB, VV, H2);
}

// round 8
// speedup vs baseline: 1.9007x; 1.0528x over previous
#include <cuda_runtime.h>
#include <cstdint>

// Problem dims
#define BB 32
#define SS 64
#define TT 48
#define TM 47      // T-1 decoder steps
#define VV 32000
#define EE 512
#define HH 1024
#define H3 3072
#define H2 2048
#define KSPLIT 4
#define PARTSZ ((size_t)BB * H3)

// ---------------- scratch (device global, no allocs) ----------------
#define OFF_EMBS   0ull                                   // [b][s][e]
#define OFF_GI0    (OFF_EMBS   + (size_t)BB*SS*EE)        // [t][b][n]
#define OFF_H0SEQ  (OFF_GI0    + (size_t)BB*SS*H3)        // [b][t][h]
#define OFF_GI1    (OFF_H0SEQ  + (size_t)BB*SS*HH)        // [t][b][n]
#define OFF_ENCOUT (OFF_GI1    + (size_t)BB*SS*H3)        // [b][t][h]
#define OFF_PROJ   (OFF_ENCOUT + (size_t)BB*SS*HH)        // [b][s][h]
#define OFF_EMBT   (OFF_PROJ   + (size_t)BB*SS*HH)        // rows m=t*B+b
#define OFF_EPRE   (OFF_EMBT   + (size_t)TM*BB*EE)        // [t][b][n]
#define OFF_CAT    (OFF_EPRE   + (size_t)TM*BB*H3)        // rows m=t*B+b, [d1|ctx]
#define OFF_H0A    (OFF_CAT    + (size_t)TM*BB*H2)        // state [b][h] row-major
#define OFF_H0B    (OFF_H0A    + (size_t)BB*HH)
#define OFF_H1A    (OFF_H0B    + (size_t)BB*HH)
#define OFF_H1B    (OFF_H1A    + (size_t)BB*HH)
#define OFF_CTXT   (OFF_H1B    + (size_t)BB*HH)           // ctx [b][h]
#define OFF_PART   (OFF_CTXT   + (size_t)BB*HH)           // 16 partial slabs [b][n]
#define OFF_WT     (OFF_PART   + 16*PARTSZ)               // 6 transposed weights [k][n]
#define WT_SZ      ((size_t)HH * H3)
#define SCRATCH_TOTAL (OFF_WT + 6*WT_SZ)

__device__ float g_scratch[SCRATCH_TOTAL];

// ---------------- small helpers ----------------
__device__ __forceinline__ float4 ld4(const float* p) {
    return *reinterpret_cast<const float4*>(p);
}
__device__ __forceinline__ void st4(float* p, float4 v) {
    *reinterpret_cast<float4*>(p) = v;
}

__global__ void zero_kernel(float* p, int n) {
    int i = blockIdx.x * blockDim.x + threadIdx.x;
    if (i < n) p[i] = 0.f;
}

__global__ void embed_enc_kernel(const int* __restrict__ ids,
                                 const float* __restrict__ table,
                                 float* __restrict__ out) {
    int i = blockIdx.x * blockDim.x + threadIdx.x;
    if (i >= BB * SS * EE) return;
    int tok = i / EE;
    int e = i % EE;
    out[i] = table[(size_t)ids[tok] * EE + e];
}

__global__ void embed_dec_kernel(const int* __restrict__ tgt,
                                 const float* __restrict__ table,
                                 float* __restrict__ out) {
    int i = blockIdx.x * blockDim.x + threadIdx.x;
    if (i >= TM * BB * EE) return;
    int m = i / EE;
    int e = i % EE;
    int t = m / BB;
    int b = m % BB;
    out[i] = table[(size_t)tgt[b * TT + t] * EE + e];
}

// one launch transposes all 6 recurrent weight matrices: Wt[k][n] = W[n][koff+k]
__global__ void transpose_all(const float* __restrict__ w0, const float* __restrict__ w1,
                              const float* __restrict__ w2, const float* __restrict__ w3,
                              const float* __restrict__ w4, const float* __restrict__ w5,
                              float* __restrict__ wt_base) {
    __shared__ float s[32][33];
    const int z = blockIdx.z;
    const float* W = (z == 0) ? w0 : (z == 1) ? w1 : (z == 2) ? w2
                   : (z == 3) ? w3 : (z == 4) ? w4 : w5;
    const int ldw = (z == 4) ? (EE + HH) : HH;
    const int koff = (z == 4) ? EE : 0;
    float* Wt = wt_base + (size_t)z * WT_SZ;
    int n0 = blockIdx.x * 32, k0 = blockIdx.y * 32;
    int tx = threadIdx.x & 31, ty = threadIdx.x >> 5;
#pragma unroll
    for (int i = 0; i < 4; i++)
        s[ty + i * 8][tx] = W[(size_t)(n0 + ty + i * 8) * ldw + koff + k0 + tx];
    __syncthreads();
#pragma unroll
    for (int i = 0; i < 4; i++)
        Wt[(size_t)(k0 + ty + i * 8) * H3 + n0 + tx] = s[tx][ty + i * 8];
}

// ---------------- tf32 helpers ----------------
__device__ __forceinline__ uint32_t f2tf(float f) {
    uint32_t u;
    asm("cvt.rna.tf32.f32 %0, %1;" : "=r"(u) : "f"(f));
    return u;
}

// ---------------- tf32 GEMM (batched projections; 128x128, 4 warps) ----------------
#define MODE_NORM 0
#define MODE_TENC 2   // m = b*64+t -> out row t*32+b (row-major [t][b][n])

template <int MODE>
__global__ void __launch_bounds__(256)
gemm_tf32(const float* __restrict__ A, int lda,
          const float* __restrict__ W, int ldw,
          const float* __restrict__ bias,
          float* __restrict__ C, int M, int N, int K) {
    __shared__ uint32_t As[32][132];   // [k][m]
    __shared__ uint32_t Ws[32][132];   // [k][n]
    const int bm = blockIdx.y * 128, bn = blockIdx.x * 128;
    const int tid = threadIdx.x;
    const int warp = tid >> 5, lane = tid & 31;
    const int wm = (warp & 1) * 64, wn = (warp >> 1) * 32;
    const int g = lane >> 2, tig = lane & 3;

    float acc[4][4][4];
#pragma unroll
    for (int a = 0; a < 4; a++)
#pragma unroll
        for (int b = 0; b < 4; b++)
#pragma unroll
            for (int c = 0; c < 4; c++) acc[a][b][c] = 0.f;

    float4 pa[4], pw[4];
#pragma unroll
    for (int i = 0; i < 4; i++) {
        int e = tid + i * 256;
        int m = e >> 3, kq = (e & 7) * 4;
        float4 v = make_float4(0.f, 0.f, 0.f, 0.f);
        if (bm + m < M) v = ld4(A + (size_t)(bm + m) * lda + kq);
        pa[i] = v;
        pw[i] = ld4(W + (size_t)(bn + m) * ldw + kq);
    }
#pragma unroll
    for (int i = 0; i < 4; i++) {
        int e = tid + i * 256;
        int m = e >> 3, kq = (e & 7) * 4;
        As[kq + 0][m] = f2tf(pa[i].x); As[kq + 1][m] = f2tf(pa[i].y);
        As[kq + 2][m] = f2tf(pa[i].z); As[kq + 3][m] = f2tf(pa[i].w);
        Ws[kq + 0][m] = f2tf(pw[i].x); Ws[kq + 1][m] = f2tf(pw[i].y);
        Ws[kq + 2][m] = f2tf(pw[i].z); Ws[kq + 3][m] = f2tf(pw[i].w);
    }
    __syncthreads();

    for (int k0 = 0; k0 < K; k0 += 32) {
        bool has_next = (k0 + 32) < K;
        if (has_next) {
#pragma unroll
            for (int i = 0; i < 4; i++) {
                int e = tid + i * 256;
                int m = e >> 3, kq = (e & 7) * 4;
                float4 v = make_float4(0.f, 0.f, 0.f, 0.f);
                if (bm + m < M) v = ld4(A + (size_t)(bm + m) * lda + k0 + 32 + kq);
                pa[i] = v;
                pw[i] = ld4(W + (size_t)(bn + m) * ldw + k0 + 32 + kq);
            }
        }
#pragma unroll
        for (int kk = 0; kk < 32; kk += 8) {
            uint32_t af[4][4];
#pragma unroll
            for (int mt = 0; mt < 4; mt++) {
                int ml = wm + mt * 16 + g;
                af[mt][0] = As[kk + tig][ml];
                af[mt][1] = As[kk + tig][ml + 8];
                af[mt][2] = As[kk + tig + 4][ml];
                af[mt][3] = As[kk + tig + 4][ml + 8];
            }
            uint32_t bf[4][2];
#pragma unroll
            for (int nt = 0; nt < 4; nt++) {
                int nl = wn + nt * 8 + g;
                bf[nt][0] = Ws[kk + tig][nl];
                bf[nt][1] = Ws[kk + tig + 4][nl];
            }
#pragma unroll
            for (int mt = 0; mt < 4; mt++)
#pragma unroll
                for (int nt = 0; nt < 4; nt++) {
                    asm volatile(
                        "mma.sync.aligned.m16n8k8.row.col.f32.tf32.tf32.f32 "
                        "{%0,%1,%2,%3}, {%4,%5,%6,%7}, {%8,%9}, {%0,%1,%2,%3};\n"
                        : "+f"(acc[mt][nt][0]), "+f"(acc[mt][nt][1]),
                          "+f"(acc[mt][nt][2]), "+f"(acc[mt][nt][3])
                        : "r"(af[mt][0]), "r"(af[mt][1]), "r"(af[mt][2]), "r"(af[mt][3]),
                          "r"(bf[nt][0]), "r"(bf[nt][1]));
                }
        }
        __syncthreads();
        if (has_next) {
#pragma unroll
            for (int i = 0; i < 4; i++) {
                int e = tid + i * 256;
                int m = e >> 3, kq = (e & 7) * 4;
                As[kq + 0][m] = f2tf(pa[i].x); As[kq + 1][m] = f2tf(pa[i].y);
                As[kq + 2][m] = f2tf(pa[i].z); As[kq + 3][m] = f2tf(pa[i].w);
                Ws[kq + 0][m] = f2tf(pw[i].x); Ws[kq + 1][m] = f2tf(pw[i].y);
                Ws[kq + 2][m] = f2tf(pw[i].z); Ws[kq + 3][m] = f2tf(pw[i].w);
            }
            __syncthreads();
        }
    }

#pragma unroll
    for (int mt = 0; mt < 4; mt++) {
#pragma unroll
        for (int i2 = 0; i2 < 2; i2++) {
            int m = bm + wm + mt * 16 + g + i2 * 8;
            if (m >= M) continue;
            size_t row;
            if (MODE == MODE_TENC) {
                int t = m & 63, b = m >> 6;
                row = (size_t)(t * BB + b);
            } else {
                row = (size_t)m;
            }
            float* cr = C + row * N;
#pragma unroll
            for (int nt = 0; nt < 4; nt++) {
#pragma unroll
                for (int j = 0; j < 2; j++) {
                    int n = bn + wn + nt * 8 + tig * 2 + j;
                    float v = acc[mt][nt][i2 * 2 + j];
                    if (bias) v += bias[n];
                    cr[n] = v;
                }
            }
        }
    }
}

// ---------------- final projection: 128x256 tile, 8 warps, m-major grid ----------------
#define FSM_WORDS (128 * 36 + 256 * 36)
#define FSM_BYTES (FSM_WORDS * 4)

__global__ void __launch_bounds__(256)
gemm_final(const float* __restrict__ A, int lda,
           const float* __restrict__ W, int ldw,
           const float* __restrict__ bias,
           float* __restrict__ C, int M, int N, int K) {
    extern __shared__ uint32_t sm[];
    uint32_t* As = sm;               // [128][36]
    uint32_t* Ws = sm + 128 * 36;    // [256][36]
    const int bm = blockIdx.x * 128;   // m-major: W streams from DRAM once
    const int bn = blockIdx.y * 256;
    const int tid = threadIdx.x;
    const int warp = tid >> 5, lane = tid & 31;
    const int wm = (warp & 1) * 64, wn = (warp >> 1) * 64;
    const int g = lane >> 2, tig = lane & 3;

    float acc[4][8][4];
#pragma unroll
    for (int a = 0; a < 4; a++)
#pragma unroll
        for (int b = 0; b < 8; b++)
#pragma unroll
            for (int c = 0; c < 4; c++) acc[a][b][c] = 0.f;

    const int kq = (tid & 7) * 4;
    float4 pa[4], pw[8];

#define LDA_CHUNK(K0)                                                        \
    _Pragma("unroll") for (int i = 0; i < 4; i++) {                          \
        int e = tid + i * 256;                                               \
        int m = e >> 3;                                                      \
        float4 v = make_float4(0.f, 0.f, 0.f, 0.f);                          \
        if (bm + m < M) v = ld4(A + (size_t)(bm + m) * lda + (K0) + kq);     \
        pa[i] = v;                                                           \
    }
#define LDW_CHUNK(K0)                                                        \
    _Pragma("unroll") for (int i = 0; i < 8; i++) {                          \
        int e = tid + i * 256;                                               \
        int n = e >> 3;                                                      \
        pw[i] = ld4(W + (size_t)(bn + n) * ldw + (K0) + kq);                 \
    }
#define ST_CHUNK()                                                           \
    _Pragma("unroll") for (int i = 0; i < 4; i++) {                          \
        int e = tid + i * 256;                                               \
        int m = e >> 3;                                                      \
        uint4 u = make_uint4(f2tf(pa[i].x), f2tf(pa[i].y),                   \
                             f2tf(pa[i].z), f2tf(pa[i].w));                  \
        *reinterpret_cast<uint4*>(&As[m * 36 + kq]) = u;                     \
    }                                                                        \
    _Pragma("unroll") for (int i = 0; i < 8; i++) {                          \
        int e = tid + i * 256;                                               \
        int n = e >> 3;                                                      \
        uint4 u = make_uint4(f2tf(pw[i].x), f2tf(pw[i].y),                   \
                             f2tf(pw[i].z), f2tf(pw[i].w));                  \
        *reinterpret_cast<uint4*>(&Ws[n * 36 + kq]) = u;                     \
    }

    LDA_CHUNK(0)
    LDW_CHUNK(0)
    ST_CHUNK()
    __syncthreads();

    for (int k0 = 0; k0 < K; k0 += 32) {
        bool has_next = (k0 + 32) < K;
        if (has_next) {
            LDA_CHUNK(k0 + 32)
            LDW_CHUNK(k0 + 32)
        }
#pragma unroll
        for (int kk = 0; kk < 32; kk += 8) {
            uint32_t af[4][4];
#pragma unroll
            for (int mt = 0; mt < 4; mt++) {
                int ml = wm + mt * 16 + g;
                af[mt][0] = As[ml * 36 + kk + tig];
                af[mt][1] = As[(ml + 8) * 36 + kk + tig];
                af[mt][2] = As[ml * 36 + kk + tig + 4];
                af[mt][3] = As[(ml + 8) * 36 + kk + tig + 4];
            }
            uint32_t bf[8][2];
#pragma unroll
            for (int nt = 0; nt < 8; nt++) {
                int nl = wn + nt * 8 + g;
                bf[nt][0] = Ws[nl * 36 + kk + tig];
                bf[nt][1] = Ws[nl * 36 + kk + tig + 4];
            }
#pragma unroll
            for (int mt = 0; mt < 4; mt++)
#pragma unroll
                for (int nt = 0; nt < 8; nt++) {
                    asm volatile(
                        "mma.sync.aligned.m16n8k8.row.col.f32.tf32.tf32.f32 "
                        "{%0,%1,%2,%3}, {%4,%5,%6,%7}, {%8,%9}, {%0,%1,%2,%3};\n"
                        : "+f"(acc[mt][nt][0]), "+f"(acc[mt][nt][1]),
                          "+f"(acc[mt][nt][2]), "+f"(acc[mt][nt][3])
                        : "r"(af[mt][0]), "r"(af[mt][1]), "r"(af[mt][2]), "r"(af[mt][3]),
                          "r"(bf[nt][0]), "r"(bf[nt][1]));
                }
        }
        __syncthreads();
        if (has_next) {
            ST_CHUNK()
            __syncthreads();
        }
    }

    // epilogue: rows m = t*32+b -> out row b*TM + t
#pragma unroll
    for (int mt = 0; mt < 4; mt++) {
#pragma unroll
        for (int i2 = 0; i2 < 2; i2++) {
            int m = bm + wm + mt * 16 + g + i2 * 8;
            if (m >= M) continue;
            int b = m & 31, t = m >> 5;
            float* cr = C + (size_t)(b * TM + t) * N;
#pragma unroll
            for (int nt = 0; nt < 8; nt++) {
#pragma unroll
                for (int j = 0; j < 2; j++) {
                    int n = bn + wn + nt * 8 + tig * 2 + j;
                    cr[n] = acc[mt][nt][i2 * 2 + j] + bias[n];
                }
            }
        }
    }
#undef LDA_CHUNK
#undef LDW_CHUNK
#undef ST_CHUNK
}

// ---------------- recurrent small GEMM v2 ----------------
// A row-major [b][1024]; Wt [k][n] stride H3. grid (48, KSPLIT, nmat).
// Block: n-range 64, k-chunk 256. Writes slab [b][n] (row-major, float4).
__global__ void __launch_bounds__(256)
rec_gemm(const float* __restrict__ A0, const float* __restrict__ W0,
         const float* __restrict__ A1, const float* __restrict__ W1,
         const float* __restrict__ A2, const float* __restrict__ W2,
         float* __restrict__ part) {
    const int z = blockIdx.z;
    const float* At = (z == 0) ? A0 : (z == 1) ? A1 : A2;
    const float* Wt = (z == 0) ? W0 : (z == 1) ? W1 : W2;
    __shared__ float sA[256 * 33];
    const int n0 = blockIdx.x * 64;
    const int k0 = blockIdx.y * 256;
    const int tid = threadIdx.x;

    // load A chunk [32 b][256 k] (row-major, coalesced) -> sA[k][b] padded
    {
        const int b = tid >> 3;
        const int q0 = tid & 7;
#pragma unroll
        for (int p = 0; p < 8; p++) {
            int q = q0 + p * 8;
            float4 v = ld4(At + (size_t)b * HH + k0 + q * 4);
            sA[(q * 4 + 0) * 33 + b] = v.x;
            sA[(q * 4 + 1) * 33 + b] = v.y;
            sA[(q * 4 + 2) * 33 + b] = v.z;
            sA[(q * 4 + 3) * 33 + b] = v.w;
        }
    }
    __syncthreads();

    const int nq = (tid & 15) * 4;
    const int b0 = (tid >> 4) * 2;
    float4 acc0 = make_float4(0.f, 0.f, 0.f, 0.f);
    float4 acc1 = make_float4(0.f, 0.f, 0.f, 0.f);
    const float* wp = Wt + (size_t)k0 * H3 + n0 + nq;
    for (int k8 = 0; k8 < 256; k8 += 8) {
        float4 w[8];
#pragma unroll
        for (int i = 0; i < 8; i++)
            w[i] = ld4(wp + (size_t)(k8 + i) * H3);
#pragma unroll
        for (int i = 0; i < 8; i++) {
            float a0 = sA[(k8 + i) * 33 + b0];
            float a1 = sA[(k8 + i) * 33 + b0 + 1];
            acc0.x += a0 * w[i].x; acc0.y += a0 * w[i].y;
            acc0.z += a0 * w[i].z; acc0.w += a0 * w[i].w;
            acc1.x += a1 * w[i].x; acc1.y += a1 * w[i].y;
            acc1.z += a1 * w[i].z; acc1.w += a1 * w[i].w;
        }
    }
    float* P = part + (size_t)(z * KSPLIT + blockIdx.y) * PARTSZ;
    st4(P + (size_t)b0 * H3 + n0 + nq, acc0);
    st4(P + (size_t)(b0 + 1) * H3 + n0 + nq, acc1);
}

// ---------------- GRU gate v2: all row-major, fully coalesced ----------------
// grid 128: b = blk>>2, h = (blk&3)*256 + tid
__global__ void __launch_bounds__(256)
gru_gate(const float* __restrict__ partH,
         const float* __restrict__ partX,       // nullable
         const float* __restrict__ gi_slab,     // nullable [b][n] slab
         const float* __restrict__ gi_vec,      // nullable (bih)
         const float* __restrict__ bhh,
         const float* __restrict__ h_in,        // [b][h]
         float* __restrict__ h_out,             // [b][h]
         float* __restrict__ seq_row, int seq_stride,  // nullable, [b*stride + h]
         float* __restrict__ cat_row)           // nullable, + b*H2 + h
{
    const int b = blockIdx.x >> 2;
    const int h = (blockIdx.x & 3) * 256 + threadIdx.x;
    float gr = 0.f, gz = 0.f, gn = 0.f;
    if (gi_slab) {
        const float* G = gi_slab + (size_t)b * H3;
        gr = G[h]; gz = G[HH + h]; gn = G[2 * HH + h];
    }
    if (gi_vec) { gr += gi_vec[h]; gz += gi_vec[HH + h]; gn += gi_vec[2 * HH + h]; }
    float hr = bhh[h], hz = bhh[HH + h], hn = bhh[2 * HH + h];
#pragma unroll
    for (int j = 0; j < KSPLIT; j++) {
        const float* P = partH + (size_t)j * PARTSZ + (size_t)b * H3;
        hr += P[h]; hz += P[HH + h]; hn += P[2 * HH + h];
    }
    if (partX) {
#pragma unroll
        for (int j = 0; j < KSPLIT; j++) {
            const float* P = partX + (size_t)j * PARTSZ + (size_t)b * H3;
            gr += P[h]; gz += P[HH + h]; gn += P[2 * HH + h];
        }
    }
    float r = 1.f / (1.f + expf(-(gr + hr)));
    float z = 1.f / (1.f + expf(-(gz + hz)));
    float n = tanhf(gn + r * hn);
    float hp = h_in[(size_t)b * HH + h];
    float out = (1.f - z) * n + z * hp;
    h_out[(size_t)b * HH + h] = out;
    if (seq_row) seq_row[(size_t)b * seq_stride + h] = out;
    if (cat_row) cat_row[(size_t)b * H2 + h] = out;
}

// ---------------- attention (state row-major now) ----------------
__global__ void __launch_bounds__(256)
attn_kernel(const float* __restrict__ proj,
            const float* __restrict__ encout,
            const float* __restrict__ d1,       // [b][h] row-major (= h1 state)
            const int* __restrict__ src_ids,
            float* __restrict__ ctxt,           // [b][h]
            float* __restrict__ catrow) {       // + b*H2 + HH + h
    int b = blockIdx.x;
    __shared__ float sc[SS];
    int tid = threadIdx.x;
    int lane = tid & 31;
    int warp = tid >> 5;
    const float* d1b = d1 + (size_t)b * HH;

    for (int s = warp; s < SS; s += 8) {
        const float* pr = proj + ((size_t)b * SS + s) * HH;
        float p = 0.f;
#pragma unroll
        for (int j = 0; j < 8; j++) {
            int k0 = j * 128 + lane * 4;
            float4 dv = ld4(d1b + k0);
            float4 pv = ld4(pr + k0);
            p += dv.x * pv.x + dv.y * pv.y + dv.z * pv.z + dv.w * pv.w;
        }
#pragma unroll
        for (int o = 16; o; o >>= 1) p += __shfl_xor_sync(0xffffffffu, p, o);
        if (lane == 0) sc[s] = (src_ids[b * SS + s] != 0) ? p : -1e9f;
    }
    __syncthreads();
    if (warp == 0) {
        float v0 = sc[lane], v1 = sc[lane + 32];
        float m = fmaxf(v0, v1);
#pragma unroll
        for (int o = 16; o; o >>= 1) m = fmaxf(m, __shfl_xor_sync(0xffffffffu, m, o));
        float e0 = expf(v0 - m), e1 = expf(v1 - m);
        float su = e0 + e1;
#pragma unroll
        for (int o = 16; o; o >>= 1) su += __shfl_xor_sync(0xffffffffu, su, o);
        sc[lane] = e0 / su;
        sc[lane + 32] = e1 / su;
    }
    __syncthreads();
    for (int h = tid; h < HH; h += 256) {
        const float* eb = encout + (size_t)b * SS * HH + h;
        float a = 0.f;
#pragma unroll 8
        for (int s = 0; s < SS; s++) a += sc[s] * eb[(size_t)s * HH];
        ctxt[(size_t)b * HH + h] = a;
        catrow[(size_t)b * H2 + HH + h] = a;
    }
}

// ---------------- host launcher ----------------
extern "C" void kernel_launch(void* const* d_in, const int* in_sizes, int n_in,
                              void* d_out, int out_size) {
    const int*   src_ids  = (const int*)d_in[0];
    const int*   tgt_ids  = (const int*)d_in[2];
    const float* enc_emb  = (const float*)d_in[3];
    const float* dec_emb  = (const float*)d_in[4];
    const float* enc_wih0 = (const float*)d_in[5];
    const float* enc_whh0 = (const float*)d_in[6];
    const float* enc_bih0 = (const float*)d_in[7];
    const float* enc_bhh0 = (const float*)d_in[8];
    const float* enc_wih1 = (const float*)d_in[9];
    const float* enc_whh1 = (const float*)d_in[10];
    const float* enc_bih1 = (const float*)d_in[11];
    const float* enc_bhh1 = (const float*)d_in[12];
    const float* dec_wih0 = (const float*)d_in[13];
    const float* dec_whh0 = (const float*)d_in[14];
    const float* dec_bih0 = (const float*)d_in[15];
    const float* dec_bhh0 = (const float*)d_in[16];
    const float* dec_wih1 = (const float*)d_in[17];
    const float* dec_whh1 = (const float*)d_in[18];
    const float* dec_bih1 = (const float*)d_in[19];
    const float* dec_bhh1 = (const float*)d_in[20];
    const float* attn_w   = (const float*)d_in[21];
    const float* out_w    = (const float*)d_in[22];
    const float* out_b    = (const float*)d_in[23];
    float* out = (float*)d_out;

    float* base = nullptr;
    cudaGetSymbolAddress((void**)&base, g_scratch);
    float* embS   = base + OFF_EMBS;
    float* gi0    = base + OFF_GI0;
    float* h0seq  = base + OFF_H0SEQ;
    float* gi1    = base + OFF_GI1;
    float* encout = base + OFF_ENCOUT;
    float* proj   = base + OFF_PROJ;
    float* embT   = base + OFF_EMBT;
    float* epre   = base + OFF_EPRE;
    float* cat    = base + OFF_CAT;
    float* h0A    = base + OFF_H0A;
    float* h0B    = base + OFF_H0B;
    float* h1A    = base + OFF_H1A;
    float* h1B    = base + OFF_H1B;
    float* ctxt   = base + OFF_CTXT;
    float* part   = base + OFF_PART;
    float* wt_ewhh0  = base + OFF_WT + 0 * WT_SZ;
    float* wt_ewhh1  = base + OFF_WT + 1 * WT_SZ;
    float* wt_dwhh0  = base + OFF_WT + 2 * WT_SZ;
    float* wt_dwhh1  = base + OFF_WT + 3 * WT_SZ;
    float* wt_dwih0c = base + OFF_WT + 4 * WT_SZ;
    float* wt_dwih1  = base + OFF_WT + 5 * WT_SZ;

    cudaFuncSetAttribute(gemm_final, cudaFuncAttributeMaxDynamicSharedMemorySize, FSM_BYTES);

    transpose_all<<<dim3(H3 / 32, HH / 32, 6), 256>>>(
        enc_whh0, enc_whh1, dec_whh0, dec_whh1, dec_wih0, dec_wih1, base + OFF_WT);
    embed_enc_kernel<<<(BB * SS * EE + 255) / 256, 256>>>(src_ids, enc_emb, embS);
    embed_dec_kernel<<<(TM * BB * EE + 255) / 256, 256>>>(tgt_ids, dec_emb, embT);
    gemm_tf32<MODE_TENC><<<dim3(H3 / 128, 16), 256>>>(
        embS, EE, enc_wih0, EE, enc_bih0, gi0, BB * SS, H3, EE);
    zero_kernel<<<(4 * BB * HH + 255) / 256, 256>>>(h0A, 4 * BB * HH);

    float* h0_cur = h0A; float* h0_nxt = h0B;
    float* h1_cur = h1A; float* h1_nxt = h1B;

    // layer-0 scan
    for (int t = 0; t < SS; t++) {
        rec_gemm<<<dim3(48, KSPLIT, 1), 256>>>(h0_cur, wt_ewhh0,
                                               nullptr, nullptr, nullptr, nullptr, part);
        gru_gate<<<128, 256>>>(part, nullptr,
                               gi0 + (size_t)t * BB * H3, nullptr, enc_bhh0,
                               h0_cur, h0_nxt,
                               h0seq + (size_t)t * HH, SS * HH, nullptr);
        float* tmp = h0_cur; h0_cur = h0_nxt; h0_nxt = tmp;
    }
    gemm_tf32<MODE_TENC><<<dim3(H3 / 128, 16), 256>>>(
        h0seq, HH, enc_wih1, HH, enc_bih1, gi1, BB * SS, H3, HH);
    // layer-1 scan
    for (int t = 0; t < SS; t++) {
        rec_gemm<<<dim3(48, KSPLIT, 1), 256>>>(h1_cur, wt_ewhh1,
                                               nullptr, nullptr, nullptr, nullptr, part);
        gru_gate<<<128, 256>>>(part, nullptr,
                               gi1 + (size_t)t * BB * H3, nullptr, enc_bhh1,
                               h1_cur, h1_nxt,
                               encout + (size_t)t * HH, SS * HH, nullptr);
        float* tmp = h1_cur; h1_cur = h1_nxt; h1_nxt = tmp;
    }
    // proj = encout @ attn_w^T
    gemm_tf32<MODE_NORM><<<dim3(HH / 128, 16), 256>>>(
        encout, HH, attn_w, HH, nullptr, proj, BB * SS, HH, HH);

    // epre = embT @ dec_wih0[:, :E]^T + dec_bih0 (rows m=t*32+b -> row-major [t][b][n])
    gemm_tf32<MODE_NORM><<<dim3(H3 / 128, (TM * BB + 127) / 128), 256>>>(
        embT, EE, dec_wih0, EE + HH, dec_bih0, epre, TM * BB, H3, EE);

    // ---- decoder loop ----
    for (int t = 0; t < TM; t++) {
        float* epre_t = epre + (size_t)t * BB * H3;
        float* cat_t  = cat + (size_t)t * BB * H2;
        attn_kernel<<<BB, 256>>>(proj, encout, h1_cur, src_ids, ctxt, cat_t);
        // z0: h0@whh0 (slabs 0-3), z1: ctx@wih0c (4-7), z2: h1@whh1 (8-11)
        rec_gemm<<<dim3(48, KSPLIT, 3), 256>>>(h0_cur, wt_dwhh0, ctxt, wt_dwih0c,
                                               h1_cur, wt_dwhh1, part);
        gru_gate<<<128, 256>>>(part, part + 4 * PARTSZ,
                               epre_t, nullptr, dec_bhh0,
                               h0_cur, h0_nxt, nullptr, 0, nullptr);
        // x-side layer 1: h0' @ wih1 -> slabs 12-15
        rec_gemm<<<dim3(48, KSPLIT, 1), 256>>>(h0_nxt, wt_dwih1,
                                               nullptr, nullptr, nullptr, nullptr,
                                               part + 12 * PARTSZ);
        gru_gate<<<128, 256>>>(part + 8 * PARTSZ, part + 12 * PARTSZ,
                               nullptr, dec_bih1, dec_bhh1,
                               h1_cur, h1_nxt, nullptr, 0, cat_t);
        float* tmp;
        tmp = h0_cur; h0_cur = h0_nxt; h0_nxt = tmp;
        tmp = h1_cur; h1_cur = h1_nxt; h1_nxt = tmp;
    }

    // ---- final projection: logits = cat @ out_w^T + out_b -> (B, TM, V) ----
    gemm_final<<<dim3((TM * BB + 127) / 128, VV / 256), 256, FSM_BYTES>>>(
        cat, H2, out_w, H2, out_b, out, TM * BB, VV, H2);
}